// round 17
// baseline (speedup 1.0000x reference)
#include <cuda_runtime.h>
#include <cuda_fp16.h>
#include <mma.h>
#include <cstdint>

using namespace nvcuda;

#define BATCH 4
#define SEQ   4096
#define CH    1024
#define NHEAD 16
#define DH    64
#define MROWS (BATCH*SEQ)     /* 16384 */
#define KDIM  CH              /* 1024  */
#define NQKV  (3*CH)          /* 3072  */
#define NSPLIT 16
#define BHCNT (BATCH*NHEAD)   /* 64    */

// GEMM tiling
#define BM 128
#define BN 128
#define BK 32
#define NT (KDIM/BK)            /* 32 K-tiles */
#define STAGES 4
#define LDA 40                  /* half elems; 80 B row stride (16B-aligned) */
#define ARR_BYTES (128*LDA*2)   /* 10240 B per array (A/B)                  */
#define STAGE_BYTES (2*ARR_BYTES)          /* 20480 */
#define GEMM_SMEM (STAGES*STAGE_BYTES)     /* 81920 -> 2 CTAs/SM = 160 KB   */

// ------------------------- scratch (device globals; no allocs) -------------------------
__device__ __half g_xh[(size_t)MROWS*KDIM];
__device__ __half g_wqkvh[(size_t)NQKV*KDIM];
__device__ __half g_wouth[(size_t)CH*KDIM];
__device__ __half g_qkvh[(size_t)MROWS*NQKV];          // q,k (feat applied), v — fp16
__device__ float  g_kv_part[(size_t)NSPLIT*BHCNT*DH*DH];
__device__ float  g_ksum_part[(size_t)NSPLIT*BHCNT*DH];
__device__ float  g_kv[(size_t)BHCNT*DH*DH];
__device__ __half g_attn_h[(size_t)MROWS*CH];

// ------------------------- helpers -------------------------
__device__ __forceinline__ uint32_t smem_u32(const void* p) {
    uint32_t a;
    asm("{ .reg .u64 t; cvta.to.shared.u64 t, %1; cvt.u32.u64 %0, t; }" : "=r"(a) : "l"(p));
    return a;
}
__device__ __forceinline__ void cp_async16(uint32_t s, const void* g) {
    asm volatile("cp.async.cg.shared.global [%0], [%1], 16;" :: "r"(s), "l"(g) : "memory");
}
__device__ __forceinline__ void cp_commit() {
    asm volatile("cp.async.commit_group;" ::: "memory");
}
template<int N>
__device__ __forceinline__ void cp_wait() {
    asm volatile("cp.async.wait_group %0;" :: "n"(N) : "memory");
}
__device__ __forceinline__ float featf(float x) {
    const float s = 0.35355339059327373f;       // 64^-0.25
    return (x > 0.0f) ? (x + 1.0f) * s : __expf(x) * s;
}

// ------------------------- fused fp32 -> fp16 convert (x, w_qkv, w_out) -------------------------
#define NX (MROWS*KDIM)         /* 16777216 */
#define NW (NQKV*KDIM)          /*  3145728 */
#define NO (CH*KDIM)            /*  1048576 */
__global__ void cvt3_kernel(const float* __restrict__ x,
                            const float* __restrict__ wq,
                            const float* __restrict__ wo) {
    int i = blockIdx.x * blockDim.x + threadIdx.x;
    const int stride = gridDim.x * blockDim.x;
    for (; i < NX + NW + NO; i += stride) {
        if (i < NX)            g_xh[i]            = __float2half(x[i]);
        else if (i < NX + NW)  g_wqkvh[i - NX]    = __float2half(wq[i - NX]);
        else                   g_wouth[i - NX - NW] = __float2half(wo[i - NX - NW]);
    }
}

// ------------------------- fp16 GEMM: C[m,n] = sum_k A[m,k]*B[n,k], f32 acc -------------------------
// MODE 0: x @ wqkv^T -> g_qkvh fp16 (feat on q,k cols). MODE 1: attn @ wout^T + bias -> fp32 out.
template<int MODE>
__global__ void __launch_bounds__(256, 2) gemm_f16(float* __restrict__ CoutExt,
                                                   const float* __restrict__ bias) {
    const __half* __restrict__ Ah = (MODE == 0) ? g_xh    : g_attn_h;
    const __half* __restrict__ Bh = (MODE == 0) ? g_wqkvh : g_wouth;

    extern __shared__ __align__(16) char smem_raw[];
    const uint32_t sb = smem_u32(smem_raw);

    const int tid = threadIdx.x;
    const int wid = tid >> 5;
    const int wm_ = wid >> 2;    // 0..1 (M dir, 64 rows each)
    const int wn_ = wid & 3;     // 0..3 (N dir, 32 cols each)
    const int m0 = blockIdx.y * BM;
    const int n0 = blockIdx.x * BN;

    const char* gptr[4];
    uint32_t    sptr[4];
    #pragma unroll
    for (int j = 0; j < 4; ++j) {
        const int idx = tid + j * 256;
        const int arr = idx >> 9, r = (idx >> 2) & 127, c16 = idx & 3;
        const __half* base = (arr == 0) ? Ah : Bh;
        const int row = ((arr == 0) ? m0 : n0) + r;
        gptr[j] = (const char*)(base + (size_t)row * KDIM + c16 * 8);
        sptr[j] = sb + arr * ARR_BYTES + r * (LDA * 2) + c16 * 16;
    }

    wmma::fragment<wmma::accumulator,16,16,16,float> acc[4][2];
    #pragma unroll
    for (int i = 0; i < 4; i++)
        #pragma unroll
        for (int j = 0; j < 2; j++) wmma::fill_fragment(acc[i][j], 0.0f);

    #pragma unroll
    for (int s = 0; s < STAGES - 1; ++s) {
        const uint32_t so = (uint32_t)s * STAGE_BYTES;
        #pragma unroll
        for (int j = 0; j < 4; ++j) cp_async16(sptr[j] + so, gptr[j] + (size_t)s * (BK*2));
        cp_commit();
    }

    for (int kt = 0; kt < NT; ++kt) {
        cp_wait<STAGES - 2>();
        __syncthreads();

        const int ns = kt + STAGES - 1;
        if (ns < NT) {
            const uint32_t so = (uint32_t)(ns & (STAGES-1)) * STAGE_BYTES;
            #pragma unroll
            for (int j = 0; j < 4; ++j) cp_async16(sptr[j] + so, gptr[j] + (size_t)ns * (BK*2));
        }
        cp_commit();

        const __half* sA = (const __half*)(smem_raw + (size_t)(kt & (STAGES-1)) * STAGE_BYTES);
        const __half* sB = sA + 128*LDA;
        const __half* pA = sA + wm_*64*LDA;
        const __half* pB = sB + wn_*32*LDA;

        #pragma unroll
        for (int ks = 0; ks < BK; ks += 16) {
            wmma::fragment<wmma::matrix_a,16,16,16,__half,wmma::row_major> a[4];
            wmma::fragment<wmma::matrix_b,16,16,16,__half,wmma::col_major> b[2];
            #pragma unroll
            for (int i = 0; i < 4; i++) wmma::load_matrix_sync(a[i], pA + i*16*LDA + ks, LDA);
            #pragma unroll
            for (int j = 0; j < 2; j++) wmma::load_matrix_sync(b[j], pB + j*16*LDA + ks, LDA);
            #pragma unroll
            for (int i = 0; i < 4; i++)
                #pragma unroll
                for (int j = 0; j < 2; j++) wmma::mma_sync(acc[i][j], a[i], b[j], acc[i][j]);
        }
        __syncthreads();
    }
    cp_wait<0>();
    __syncthreads();

    float* Cs = (float*)smem_raw;   // 128 x 132 f32 = 67584 B (fits in 81920)
    #pragma unroll
    for (int i = 0; i < 4; i++)
        #pragma unroll
        for (int j = 0; j < 2; j++)
            wmma::store_matrix_sync(Cs + (wm_*64 + i*16)*132 + wn_*32 + j*16,
                                    acc[i][j], 132, wmma::mem_row_major);
    __syncthreads();
    for (int i = tid; i < BM*BN/4; i += 256) {
        const int row = i >> 5;
        const int c4  = (i & 31) << 2;
        float4 v = *(const float4*)&Cs[row*132 + c4];
        const int gn = n0 + c4;
        if (MODE == 0) {
            if (gn < 2*CH) {
                v.x = featf(v.x); v.y = featf(v.y); v.z = featf(v.z); v.w = featf(v.w);
            }
            __half* dst = g_qkvh + (size_t)(m0 + row)*NQKV + gn;
            *(__half2*)dst       = __halves2half2(__float2half(v.x), __float2half(v.y));
            *(__half2*)(dst + 2) = __halves2half2(__float2half(v.z), __float2half(v.w));
        } else {
            v.x += bias[gn]; v.y += bias[gn+1]; v.z += bias[gn+2]; v.w += bias[gn+3];
            *(float4*)&CoutExt[(size_t)(m0 + row)*CH + gn] = v;
        }
    }
}

// ------------------------- kv = k^T v partials + ksum partials (tensor core) -------------------------
// grid (NSPLIT, BHCNT), 128 threads. Per block: C[64x64] = sum over 256 rows of k^T v.
__global__ void __launch_bounds__(128) kv_partial_kernel() {
    const int s  = blockIdx.x;
    const int bh = blockIdx.y;
    const int b = bh >> 4, h = bh & 15;
    const int tid = threadIdx.x;
    const int wid = tid >> 5;

    __shared__ __align__(16) char blob[2*128*72*2];     // 36864 B
    __half* k_s = (__half*)blob;                        // 128 x 72
    __half* v_s = (__half*)(blob + 128*72*2);           // 128 x 72
    __shared__ float ks_red[2][64];

    const __half* kbase = g_qkvh + (size_t)(b*SEQ)*NQKV + CH + h*DH;
    const __half* vbase = kbase + CH;

    wmma::fragment<wmma::accumulator,16,16,16,float> acc[2][2];
    #pragma unroll
    for (int i = 0; i < 2; i++)
        #pragma unroll
        for (int j = 0; j < 2; j++) wmma::fill_fragment(acc[i][j], 0.0f);

    const int wm = wid >> 1, wn = wid & 1;   // 2x2 warp grid, 32x32 per warp
    const int dcol = tid & 63, rhalf = tid >> 6;
    float ksum = 0.0f;

    #pragma unroll
    for (int c = 0; c < 2; ++c) {
        const int nbase = s*256 + c*128;
        {
            const uint4* gk = (const uint4*)(kbase + (size_t)(nbase + tid)*NQKV);
            const uint4* gv = (const uint4*)(vbase + (size_t)(nbase + tid)*NQKV);
            uint4* sk = (uint4*)(k_s + tid*72);
            uint4* sv = (uint4*)(v_s + tid*72);
            #pragma unroll
            for (int q8 = 0; q8 < 8; ++q8) { sk[q8] = gk[q8]; sv[q8] = gv[q8]; }
        }
        __syncthreads();
        {
            float t = 0.0f;
            #pragma unroll 16
            for (int rr = 0; rr < 64; ++rr)
                t += __half2float(k_s[(rhalf*64 + rr)*72 + dcol]);
            ksum += t;
        }
        #pragma unroll
        for (int k16 = 0; k16 < 8; ++k16) {
            wmma::fragment<wmma::matrix_a,16,16,16,__half,wmma::col_major> af[2];
            wmma::fragment<wmma::matrix_b,16,16,16,__half,wmma::row_major> bf[2];
            #pragma unroll
            for (int i = 0; i < 2; i++)
                wmma::load_matrix_sync(af[i], k_s + k16*16*72 + wm*32 + i*16, 72);
            #pragma unroll
            for (int j = 0; j < 2; j++)
                wmma::load_matrix_sync(bf[j], v_s + k16*16*72 + wn*32 + j*16, 72);
            #pragma unroll
            for (int i = 0; i < 2; i++)
                #pragma unroll
                for (int j = 0; j < 2; j++) wmma::mma_sync(acc[i][j], af[i], bf[j], acc[i][j]);
        }
        __syncthreads();
    }

    ks_red[rhalf][dcol] = ksum;
    float* Cs = (float*)blob;       // 64 x 68 f32 = 17408 B
    #pragma unroll
    for (int i = 0; i < 2; i++)
        #pragma unroll
        for (int j = 0; j < 2; j++)
            wmma::store_matrix_sync(Cs + (wm*32 + i*16)*68 + wn*32 + j*16,
                                    acc[i][j], 68, wmma::mem_row_major);
    __syncthreads();
    float* outp = g_kv_part + ((size_t)s*BHCNT + bh)*(DH*DH);
    for (int i = tid; i < 64*64/4; i += 128) {
        const int row = i >> 4, c4 = (i & 15) << 2;
        *(float4*)&outp[row*64 + c4] = *(const float4*)&Cs[row*68 + c4];
    }
    if (tid < 64)
        g_ksum_part[((size_t)s*BHCNT + bh)*DH + tid] = ks_red[0][tid] + ks_red[1][tid];
}

__global__ void kv_reduce_kernel() {
    const int i = blockIdx.x * 256 + threadIdx.x;
    float s = 0.0f;
    #pragma unroll
    for (int p = 0; p < NSPLIT; ++p) s += g_kv_part[(size_t)p*(BHCNT*DH*DH) + i];
    g_kv[i] = s;
}

// ------------------------- out = (q @ kv) / (q . ksum + eps) -> fp16 (tensor core) -------------------------
// grid (32, BHCNT), 128 threads. kv split hi/lo fp16, 2-term MMA (exact).
__global__ void __launch_bounds__(128) attn_kernel() {
    const int chunk = blockIdx.x;
    const int bh = blockIdx.y;
    const int b = bh >> 4, h = bh & 15;
    const int tid = threadIdx.x;
    const int wid = tid >> 5;
    const int base = chunk * 128;

    __shared__ __align__(16) char blob[36864];
    __half* q_s   = (__half*)blob;                 // 128 x 72 = 18432 B
    __half* kvh_s = (__half*)(blob + 18432);       // 64 x 72  =  9216 B
    __half* kvl_s = (__half*)(blob + 27648);       // 64 x 72  =  9216 B
    __shared__ float ksum_s[64];
    __shared__ float inv_s[128];

    {
        const uint4* gq = (const uint4*)(g_qkvh + (size_t)(b*SEQ + base + tid)*NQKV + h*DH);
        uint4* sq = (uint4*)(q_s + tid*72);
        #pragma unroll
        for (int q8 = 0; q8 < 8; ++q8) sq[q8] = gq[q8];
    }
    for (int i = tid; i < 64*64; i += 128) {
        const int r = i >> 6, c = i & 63;
        const float v = g_kv[(size_t)bh*(DH*DH) + i];
        const __half hh = __float2half(v);
        kvh_s[r*72 + c] = hh;
        kvl_s[r*72 + c] = __float2half(v - __half2float(hh));
    }
    if (tid < 64) {
        float s = 0.0f;
        #pragma unroll
        for (int p = 0; p < NSPLIT; ++p) s += g_ksum_part[((size_t)p*BHCNT + bh)*DH + tid];
        ksum_s[tid] = s;
    }
    __syncthreads();
    {
        float a = 0.0f;
        #pragma unroll 16
        for (int d = 0; d < DH; ++d) a += __half2float(q_s[tid*72 + d]) * ksum_s[d];
        inv_s[tid] = 1.0f / (a + 1e-6f);
    }

    const int wm = wid >> 1, wn = wid & 1;
    wmma::fragment<wmma::accumulator,16,16,16,float> acc[4][2];
    #pragma unroll
    for (int i = 0; i < 4; i++)
        #pragma unroll
        for (int j = 0; j < 2; j++) wmma::fill_fragment(acc[i][j], 0.0f);
    #pragma unroll
    for (int k16 = 0; k16 < 4; ++k16) {
        wmma::fragment<wmma::matrix_a,16,16,16,__half,wmma::row_major> af[4];
        wmma::fragment<wmma::matrix_b,16,16,16,__half,wmma::row_major> bhf[2], blf[2];
        #pragma unroll
        for (int i = 0; i < 4; i++)
            wmma::load_matrix_sync(af[i], q_s + (wm*64 + i*16)*72 + k16*16, 72);
        #pragma unroll
        for (int j = 0; j < 2; j++) {
            wmma::load_matrix_sync(bhf[j], kvh_s + k16*16*72 + wn*32 + j*16, 72);
            wmma::load_matrix_sync(blf[j], kvl_s + k16*16*72 + wn*32 + j*16, 72);
        }
        #pragma unroll
        for (int i = 0; i < 4; i++)
            #pragma unroll
            for (int j = 0; j < 2; j++) wmma::mma_sync(acc[i][j], af[i], bhf[j], acc[i][j]);
        #pragma unroll
        for (int i = 0; i < 4; i++)
            #pragma unroll
            for (int j = 0; j < 2; j++) wmma::mma_sync(acc[i][j], af[i], blf[j], acc[i][j]);
    }
    __syncthreads();
    float* Cs = (float*)blob;   // 128 x 68 f32 = 34816 B
    #pragma unroll
    for (int i = 0; i < 4; i++)
        #pragma unroll
        for (int j = 0; j < 2; j++)
            wmma::store_matrix_sync(Cs + (wm*64 + i*16)*68 + wn*32 + j*16,
                                    acc[i][j], 68, wmma::mem_row_major);
    __syncthreads();
    for (int i = tid; i < 128*64/4; i += 128) {
        const int row = i >> 4, c4 = (i & 15) << 2;
        const float4 v = *(const float4*)&Cs[row*68 + c4];
        const float inv = inv_s[row];
        __half* dst = g_attn_h + (size_t)(b*SEQ + base + row)*CH + h*DH + c4;
        *(__half2*)dst       = __halves2half2(__float2half(v.x*inv), __float2half(v.y*inv));
        *(__half2*)(dst + 2) = __halves2half2(__float2half(v.z*inv), __float2half(v.w*inv));
    }
}

// ------------------------- launch -------------------------
extern "C" void kernel_launch(void* const* d_in, const int* in_sizes, int n_in,
                              void* d_out, int out_size) {
    (void)in_sizes; (void)n_in; (void)out_size;
    const float* x     = (const float*)d_in[0];
    const float* w_qkv = (const float*)d_in[1];
    const float* w_out = (const float*)d_in[2];
    const float* b_out = (const float*)d_in[3];
    float* out = (float*)d_out;

    cvt3_kernel<<<4096, 256>>>(x, w_qkv, w_out);

    cudaFuncSetAttribute(gemm_f16<0>, cudaFuncAttributeMaxDynamicSharedMemorySize, (int)GEMM_SMEM);
    gemm_f16<0><<<dim3(NQKV/BN, MROWS/BM), 256, GEMM_SMEM>>>(nullptr, nullptr);

    kv_partial_kernel<<<dim3(NSPLIT, BHCNT), 128>>>();
    kv_reduce_kernel<<<(BHCNT*DH*DH)/256, 256>>>();
    attn_kernel<<<dim3(32, BHCNT), 128>>>();

    cudaFuncSetAttribute(gemm_f16<1>, cudaFuncAttributeMaxDynamicSharedMemorySize, (int)GEMM_SMEM);
    gemm_f16<1><<<dim3(CH/BN, MROWS/BM), 256, GEMM_SMEM>>>(out, b_out);
}